// round 1
// baseline (speedup 1.0000x reference)
#include <cuda_runtime.h>
#include <cuda_bf16.h>
#include <cstddef>

#define T_Q  1024
#define B_B  2
#define S_KV 4096
#define D_D  1024
#define H_H  16
#define HD   64

// Scratch (device globals; no allocations allowed)
__device__ float g_q[(size_t)B_B * H_H * T_Q * HD];    // [B,H,T,64]   8 MB
__device__ float g_k[(size_t)B_B * H_H * S_KV * HD];   // [B,H,S,64]  32 MB
__device__ float g_v[(size_t)B_B * H_H * S_KV * HD];   // [B,H,S,64]  32 MB
__device__ float g_ctx[(size_t)B_B * T_Q * D_D];       // [B,T,D]      8 MB

// ---------------------------------------------------------------------------
// Fused projection GEMM: C = (A [+A2]) @ W^T + bias, with mode-specific
// input addressing ([seq,B,D] layouts) and epilogue (head-split permute,
// q-scaling, or final [T,B,D] output).
// MODE 0: Q proj   (A=hs,  A2=pos,   out -> g_q, *0.125)
// MODE 1: K proj   (A=kv,  A2=kvpos, out -> g_k)
// MODE 2: V proj   (A=kv,            out -> g_v)
// MODE 3: O proj   (A=g_ctx,         out -> d_out [T,B,D])
// ---------------------------------------------------------------------------
template <int MODE>
__global__ void proj_gemm(const float* __restrict__ A,
                          const float* __restrict__ A2,
                          const float* __restrict__ W,
                          const float* __restrict__ bias,
                          float* __restrict__ out,
                          int seqlen)
{
    constexpr int BM = 64, BN = 64, BK = 16;
    __shared__ __align__(16) float As[BK][BM + 4];
    __shared__ __align__(16) float Bs[BK][BN + 4];

    const int tid = threadIdx.x;         // 256 threads
    const int tx  = tid & 15;
    const int ty  = tid >> 4;
    const int m0  = blockIdx.y * BM;
    const int n0  = blockIdx.x * BN;

    float acc[4][4] = {};

    for (int k0 = 0; k0 < D_D; k0 += BK) {
        // Stage A tile (transposed into As[k][m])
        #pragma unroll
        for (int i = tid; i < BM * BK; i += 256) {
            int mm = i / BK, kk = i % BK;
            int m = m0 + mm;
            float a;
            if (MODE == 3) {
                a = g_ctx[(size_t)m * D_D + k0 + kk];
            } else {
                int b = m / seqlen, si = m % seqlen;
                size_t idx = (size_t)si * (B_B * D_D) + (size_t)b * D_D + k0 + kk;
                a = A[idx];
                if (MODE == 0 || MODE == 1) a += A2[idx];
            }
            As[kk][mm] = a;
        }
        // Stage W tile: W is [D_out, D_in] row-major, we need W[n][k]
        #pragma unroll
        for (int i = tid; i < BN * BK; i += 256) {
            int nn = i / BK, kk = i % BK;
            Bs[kk][nn] = W[(size_t)(n0 + nn) * D_D + k0 + kk];
        }
        __syncthreads();

        #pragma unroll
        for (int kk = 0; kk < BK; kk++) {
            float4 ra = *(const float4*)&As[kk][ty * 4];
            float4 rb = *(const float4*)&Bs[kk][tx * 4];
            float a4[4] = {ra.x, ra.y, ra.z, ra.w};
            float b4[4] = {rb.x, rb.y, rb.z, rb.w};
            #pragma unroll
            for (int i = 0; i < 4; i++)
                #pragma unroll
                for (int j = 0; j < 4; j++)
                    acc[i][j] = fmaf(a4[i], b4[j], acc[i][j]);
        }
        __syncthreads();
    }

    // Epilogue
    const int sl = (MODE == 3) ? T_Q : seqlen;
    #pragma unroll
    for (int i = 0; i < 4; i++) {
        int m  = m0 + ty * 4 + i;
        int b  = m / sl;
        int si = m % sl;
        #pragma unroll
        for (int j = 0; j < 4; j++) {
            int n = n0 + tx * 4 + j;
            float v = acc[i][j] + bias[n];
            if (MODE == 0) {
                v *= 0.125f;  // hd^-0.5, hd=64
                g_q[(((size_t)b * H_H + (n >> 6)) * T_Q + si) * HD + (n & 63)] = v;
            } else if (MODE == 1) {
                g_k[(((size_t)b * H_H + (n >> 6)) * S_KV + si) * HD + (n & 63)] = v;
            } else if (MODE == 2) {
                g_v[(((size_t)b * H_H + (n >> 6)) * S_KV + si) * HD + (n & 63)] = v;
            } else {
                out[(size_t)si * (B_B * D_D) + (size_t)b * D_D + n] = v;
            }
        }
    }
}

// ---------------------------------------------------------------------------
// Flash attention: per (b,h), 64 query rows per CTA, stream S in 64-tiles.
// scores = q@k^T + mask ; online softmax ; acc += p@v ; never materializes
// the [T,S] score tensor. Mask (537 MB) is streamed exactly once.
// ---------------------------------------------------------------------------
__global__ void attn_kernel(const float* __restrict__ mask)
{
    constexpr int BQ = 64, BS = 64, DH = 64, ST = 68;  // ST = padded stride
    extern __shared__ __align__(16) float sm[];
    float* Qt = sm;                 // [DH][BQ+4]  (transposed: Qt[d][r])
    float* Kt = Qt + DH * ST;       // [DH][BS+4]  (transposed: Kt[d][s])
    float* Vs = Kt + DH * ST;       // [BS][DH+4]  (natural:   Vs[s][d])
    float* Pt = Vs + BS * ST;       // [BS][BQ+4]  (transposed: Pt[s][r])

    const int tid = threadIdx.x;    // 256 threads
    const int tx  = tid & 15;
    const int ty  = tid >> 4;
    const int t0  = blockIdx.x * BQ;
    const int h   = blockIdx.y;
    const int b   = blockIdx.z;
    const int bh  = b * H_H + h;

    const float* qg = g_q + ((size_t)bh * T_Q + t0) * HD;
    const float* kg = g_k + (size_t)bh * S_KV * HD;
    const float* vg = g_v + (size_t)bh * S_KV * HD;
    const float* mg = mask + (size_t)bh * T_Q * S_KV + (size_t)t0 * S_KV;

    // Load Q tile (transposed)
    for (int i = tid; i < BQ * DH; i += 256) {
        int r = i >> 6, d = i & 63;
        Qt[d * ST + r] = qg[r * HD + d];
    }

    float acc[4][4] = {};
    float mrow[4], lrow[4];
    #pragma unroll
    for (int i = 0; i < 4; i++) { mrow[i] = -1e30f; lrow[i] = 0.f; }

    for (int s0 = 0; s0 < S_KV; s0 += BS) {
        __syncthreads();  // protect Kt/Vs from previous iteration's readers
        for (int i = tid; i < BS * DH; i += 256) {
            int r = i >> 6, d = i & 63;
            float kvald = kg[(size_t)(s0 + r) * HD + d];
            float vvald = vg[(size_t)(s0 + r) * HD + d];
            Kt[d * ST + r] = kvald;
            Vs[r * ST + d] = vvald;
        }
        __syncthreads();

        // scores tile
        float sc[4][4] = {};
        #pragma unroll 8
        for (int d = 0; d < DH; d++) {
            float4 ra = *(const float4*)&Qt[d * ST + ty * 4];
            float4 rb = *(const float4*)&Kt[d * ST + tx * 4];
            float a4[4] = {ra.x, ra.y, ra.z, ra.w};
            float b4[4] = {rb.x, rb.y, rb.z, rb.w};
            #pragma unroll
            for (int i = 0; i < 4; i++)
                #pragma unroll
                for (int j = 0; j < 4; j++)
                    sc[i][j] = fmaf(a4[i], b4[j], sc[i][j]);
        }
        // + mask
        #pragma unroll
        for (int i = 0; i < 4; i++) {
            const float* mrow_g = mg + (size_t)(ty * 4 + i) * S_KV + s0 + tx * 4;
            float4 mv = *(const float4*)mrow_g;
            sc[i][0] += mv.x; sc[i][1] += mv.y; sc[i][2] += mv.z; sc[i][3] += mv.w;
        }

        // online softmax (row state replicated across the 16 tx lanes)
        #pragma unroll
        for (int i = 0; i < 4; i++) {
            float mx = fmaxf(fmaxf(sc[i][0], sc[i][1]), fmaxf(sc[i][2], sc[i][3]));
            #pragma unroll
            for (int o = 8; o >= 1; o >>= 1)
                mx = fmaxf(mx, __shfl_xor_sync(0xffffffffu, mx, o));
            float mnew = fmaxf(mrow[i], mx);
            float scale = __expf(mrow[i] - mnew);
            float psum = 0.f;
            #pragma unroll
            for (int j = 0; j < 4; j++) {
                float p = __expf(sc[i][j] - mnew);
                sc[i][j] = p;
                psum += p;
            }
            #pragma unroll
            for (int o = 8; o >= 1; o >>= 1)
                psum += __shfl_xor_sync(0xffffffffu, psum, o);
            lrow[i] = lrow[i] * scale + psum;
            mrow[i] = mnew;
            #pragma unroll
            for (int j = 0; j < 4; j++) acc[i][j] *= scale;
        }

        // store P transposed: Pt[s][r]; float4 over the row dim
        #pragma unroll
        for (int j = 0; j < 4; j++) {
            float4 pv = make_float4(sc[0][j], sc[1][j], sc[2][j], sc[3][j]);
            *(float4*)&Pt[(tx * 4 + j) * ST + ty * 4] = pv;
        }
        __syncthreads();

        // acc += P @ V
        #pragma unroll 8
        for (int s = 0; s < BS; s++) {
            float4 rp = *(const float4*)&Pt[s * ST + ty * 4];
            float4 rv = *(const float4*)&Vs[s * ST + tx * 4];
            float p4[4] = {rp.x, rp.y, rp.z, rp.w};
            float v4[4] = {rv.x, rv.y, rv.z, rv.w};
            #pragma unroll
            for (int i = 0; i < 4; i++)
                #pragma unroll
                for (int j = 0; j < 4; j++)
                    acc[i][j] = fmaf(p4[i], v4[j], acc[i][j]);
        }
    }

    // normalize + write ctx [B,T,D]
    #pragma unroll
    for (int i = 0; i < 4; i++) {
        int r = t0 + ty * 4 + i;
        float inv = 1.f / lrow[i];
        #pragma unroll
        for (int j = 0; j < 4; j++)
            g_ctx[((size_t)b * T_Q + r) * D_D + h * HD + tx * 4 + j] = acc[i][j] * inv;
    }
}

// ---------------------------------------------------------------------------
extern "C" void kernel_launch(void* const* d_in, const int* in_sizes, int n_in,
                              void* d_out, int out_size)
{
    const float* hs    = (const float*)d_in[0];
    const float* mask  = (const float*)d_in[1];
    const float* pos   = (const float*)d_in[2];
    const float* kv    = (const float*)d_in[3];
    const float* kvpos = (const float*)d_in[4];
    const float* Wq = (const float*)d_in[5];  const float* bq = (const float*)d_in[6];
    const float* Wk = (const float*)d_in[7];  const float* bk = (const float*)d_in[8];
    const float* Wv = (const float*)d_in[9];  const float* bv = (const float*)d_in[10];
    const float* Wo = (const float*)d_in[11]; const float* bo = (const float*)d_in[12];
    float* out = (float*)d_out;

    const int attn_smem = 4 * 64 * 68 * (int)sizeof(float);  // 69632 B
    cudaFuncSetAttribute(attn_kernel, cudaFuncAttributeMaxDynamicSharedMemorySize,
                         attn_smem);

    // Q projection: M = B*T = 2048
    proj_gemm<0><<<dim3(D_D / 64, (B_B * T_Q) / 64), 256>>>(hs, pos, Wq, bq, nullptr, T_Q);
    // K projection: M = B*S = 8192
    proj_gemm<1><<<dim3(D_D / 64, (B_B * S_KV) / 64), 256>>>(kv, kvpos, Wk, bk, nullptr, S_KV);
    // V projection
    proj_gemm<2><<<dim3(D_D / 64, (B_B * S_KV) / 64), 256>>>(kv, nullptr, Wv, bv, nullptr, S_KV);
    // Attention
    attn_kernel<<<dim3(T_Q / 64, H_H, B_B), 256, attn_smem>>>(mask);
    // Output projection
    proj_gemm<3><<<dim3(D_D / 64, (B_B * T_Q) / 64), 256>>>(nullptr, nullptr, Wo, bo, out, T_Q);
}

// round 2
// speedup vs baseline: 3.0609x; 3.0609x over previous
#include <cuda_runtime.h>
#include <cuda_bf16.h>
#include <cstddef>
#include <cstdint>

#define T_Q  1024
#define B_B  2
#define S_KV 4096
#define D_D  1024
#define H_H  16
#define HD   64

// Scratch (device globals; allocations are forbidden).
// g_q/g_k/g_v hold tf32-rounded values (stored as float bits) so the
// attention kernel needs no converts in its hot loop.
__device__ __align__(256) float g_q[(size_t)B_B * H_H * T_Q * HD];    //  8 MB
__device__ __align__(256) float g_k[(size_t)B_B * H_H * S_KV * HD];   // 32 MB
__device__ __align__(256) float g_v[(size_t)B_B * H_H * S_KV * HD];   // 32 MB
__device__ __align__(256) float g_ctx[(size_t)B_B * T_Q * D_D];       //  8 MB

// ---------------------------------------------------------------------------
__device__ __forceinline__ uint32_t f2t(float f) {
    uint32_t u; asm("cvt.rna.tf32.f32 %0, %1;" : "=r"(u) : "f"(f)); return u;
}

// D += A(m16k8,tf32) * B(k8n8,tf32)
__device__ __forceinline__ void mma8(float* d, const uint32_t* a, const uint32_t* b) {
    asm volatile(
        "mma.sync.aligned.m16n8k8.row.col.f32.tf32.tf32.f32 "
        "{%0,%1,%2,%3},{%4,%5,%6,%7},{%8,%9},{%0,%1,%2,%3};"
        : "+f"(d[0]), "+f"(d[1]), "+f"(d[2]), "+f"(d[3])
        : "r"(a[0]), "r"(a[1]), "r"(a[2]), "r"(a[3]), "r"(b[0]), "r"(b[1]));
}

// ---------------------------------------------------------------------------
// Fused projection GEMM via tf32 MMA.
// C = (A [+A2]) @ W^T + bias, with mode-specific input addressing and epilogue.
// MODE 0: Q proj (hs+pos  -> g_q tf32, *0.125, head-split)
// MODE 1: K proj (kv+kvpos-> g_k tf32, head-split)
// MODE 2: V proj (kv      -> g_v tf32, head-split)
// MODE 3: O proj (g_ctx   -> d_out [T,B,D], fp32)
// ---------------------------------------------------------------------------
template <int MODE>
__global__ __launch_bounds__(256)
void proj_mma(const float* __restrict__ A, const float* __restrict__ A2,
              const float* __restrict__ W, const float* __restrict__ bias,
              float* __restrict__ out, int seqlen)
{
    constexpr int BM = 128, BN = 64, BK = 32, SA = BK + 4, SB = BK + 4;
    __shared__ __align__(16) uint32_t As[BM * SA];
    __shared__ __align__(16) uint32_t Bs[BN * SB];

    const int tid  = threadIdx.x;
    const int wid  = tid >> 5, lane = tid & 31;
    const int g    = lane >> 2, tg = lane & 3;
    const int wm   = wid >> 1, wn = wid & 1;     // 4 x 2 warp grid
    const int m0   = blockIdx.y * BM;
    const int n0   = blockIdx.x * BN;

    float acc[2][4][4] = {};

    for (int k0 = 0; k0 < D_D; k0 += BK) {
        // stage A tile (convert to tf32): 128 rows x 8 float4 => 4/thread
        #pragma unroll
        for (int it = 0; it < 4; it++) {
            int idx = tid + it * 256;
            int row = idx >> 3;
            int kc  = (idx & 7) * 4;
            int m   = m0 + row;
            float4 v;
            if (MODE == 3) {
                v = *(const float4*)&g_ctx[(size_t)m * D_D + k0 + kc];
            } else {
                int b = m / seqlen, si = m % seqlen;
                size_t base = (size_t)si * (B_B * D_D) + (size_t)b * D_D + k0 + kc;
                v = *(const float4*)&A[base];
                if (MODE == 0 || MODE == 1) {
                    float4 v2 = *(const float4*)&A2[base];
                    v.x += v2.x; v.y += v2.y; v.z += v2.z; v.w += v2.w;
                }
            }
            uint32_t* p = &As[row * SA + kc];
            p[0] = f2t(v.x); p[1] = f2t(v.y); p[2] = f2t(v.z); p[3] = f2t(v.w);
        }
        // stage W tile: 64 rows x 8 float4 => 2/thread
        #pragma unroll
        for (int it = 0; it < 2; it++) {
            int idx = tid + it * 256;
            int row = idx >> 3;
            int kc  = (idx & 7) * 4;
            float4 v = *(const float4*)&W[(size_t)(n0 + row) * D_D + k0 + kc];
            uint32_t* p = &Bs[row * SB + kc];
            p[0] = f2t(v.x); p[1] = f2t(v.y); p[2] = f2t(v.z); p[3] = f2t(v.w);
        }
        __syncthreads();

        #pragma unroll
        for (int k8 = 0; k8 < BK; k8 += 8) {
            uint32_t afr[2][4], bfr[4][2];
            #pragma unroll
            for (int im = 0; im < 2; im++) {
                int r = wm * 32 + im * 16;
                afr[im][0] = As[(r + g    ) * SA + k8 + tg];
                afr[im][1] = As[(r + g + 8) * SA + k8 + tg];
                afr[im][2] = As[(r + g    ) * SA + k8 + tg + 4];
                afr[im][3] = As[(r + g + 8) * SA + k8 + tg + 4];
            }
            #pragma unroll
            for (int jn = 0; jn < 4; jn++) {
                int c = wn * 32 + jn * 8;
                bfr[jn][0] = Bs[(c + g) * SB + k8 + tg];
                bfr[jn][1] = Bs[(c + g) * SB + k8 + tg + 4];
            }
            #pragma unroll
            for (int im = 0; im < 2; im++)
                #pragma unroll
                for (int jn = 0; jn < 4; jn++)
                    mma8(acc[im][jn], afr[im], bfr[jn]);
        }
        __syncthreads();
    }

    // epilogue: c0,c1 -> row g cols 2tg,2tg+1; c2,c3 -> row g+8
    const int sl = (MODE == 3) ? T_Q : seqlen;
    #pragma unroll
    for (int im = 0; im < 2; im++) {
        #pragma unroll
        for (int rr = 0; rr < 2; rr++) {
            int m  = m0 + wm * 32 + im * 16 + g + rr * 8;
            int b  = m / sl;
            int si = m % sl;
            #pragma unroll
            for (int jn = 0; jn < 4; jn++) {
                int n = n0 + wn * 32 + jn * 8 + 2 * tg;
                float v0 = acc[im][jn][rr * 2 + 0] + bias[n];
                float v1 = acc[im][jn][rr * 2 + 1] + bias[n + 1];
                if (MODE == 0) {
                    v0 *= 0.125f; v1 *= 0.125f;
                    size_t o = (((size_t)b * H_H + (n >> 6)) * T_Q + si) * HD + (n & 63);
                    *(float2*)&g_q[o] = make_float2(__uint_as_float(f2t(v0)),
                                                    __uint_as_float(f2t(v1)));
                } else if (MODE == 1) {
                    size_t o = (((size_t)b * H_H + (n >> 6)) * S_KV + si) * HD + (n & 63);
                    *(float2*)&g_k[o] = make_float2(__uint_as_float(f2t(v0)),
                                                    __uint_as_float(f2t(v1)));
                } else if (MODE == 2) {
                    size_t o = (((size_t)b * H_H + (n >> 6)) * S_KV + si) * HD + (n & 63);
                    *(float2*)&g_v[o] = make_float2(__uint_as_float(f2t(v0)),
                                                    __uint_as_float(f2t(v1)));
                } else {
                    *(float2*)&out[(size_t)si * (B_B * D_D) + (size_t)b * D_D + n] =
                        make_float2(v0, v1);
                }
            }
        }
    }
}

// ---------------------------------------------------------------------------
// Flash attention via tf32 MMA.
// CTA: 128 q-rows x one (b,h). 8 warps, each owns one m16 strip spanning the
// full 64-wide S tile (softmax row reduction = 2 shfls inside a lane quad).
// P round-trips through a per-warp-private smem strip (only __syncwarp).
// Mask (537 MB) streamed once, directly into C-fragment lanes as float2.
// ---------------------------------------------------------------------------
__global__ __launch_bounds__(256, 2)
void attn_mma(const float* __restrict__ mask)
{
    constexpr int BQ = 128, BS = 64;
    constexpr int SQ = 68, SK = 68, SV = 72, SP = 68;
    extern __shared__ __align__(16) uint32_t smem[];
    uint32_t* Qu = smem;                    // [128][68]
    uint32_t* Ku = Qu + BQ * SQ;            // [64][68]
    uint32_t* Vu = Ku + BS * SK;            // [64][72]
    uint32_t* Pu = Vu + BS * SV;            // [128][68]

    const int tid  = threadIdx.x;
    const int wid  = tid >> 5, lane = tid & 31;
    const int g    = lane >> 2, tg = lane & 3;
    const int t0   = blockIdx.x * BQ;
    const int bh   = blockIdx.y;
    const int r    = wid * 16;              // warp's q-row base within tile

    const float* qg = g_q + ((size_t)bh * T_Q + t0) * HD;
    const float* kg = g_k + (size_t)bh * S_KV * HD;
    const float* vg = g_v + (size_t)bh * S_KV * HD;
    const float* mg = mask + (size_t)bh * T_Q * S_KV + (size_t)t0 * S_KV;

    // stage Q (already tf32 bits): 128x64 = 2048 float4 => 8/thread
    #pragma unroll
    for (int it = 0; it < 8; it++) {
        int idx = tid + it * 256;
        int row = idx >> 4;
        int c   = (idx & 15) * 4;
        *(uint4*)&Qu[row * SQ + c] = *(const uint4*)&qg[row * HD + c];
    }

    float acc[8][4] = {};
    float mr0 = -1e30f, mr1 = -1e30f, lr0 = 0.f, lr1 = 0.f;

    for (int s0 = 0; s0 < S_KV; s0 += BS) {
        __syncthreads();
        // stage K, V: 64x64 each = 1024 float4 => 4/thread each
        #pragma unroll
        for (int it = 0; it < 4; it++) {
            int idx = tid + it * 256;
            int row = idx >> 4;
            int c   = (idx & 15) * 4;
            *(uint4*)&Ku[row * SK + c] = *(const uint4*)&kg[(size_t)(s0 + row) * HD + c];
            *(uint4*)&Vu[row * SV + c] = *(const uint4*)&vg[(size_t)(s0 + row) * HD + c];
        }
        __syncthreads();

        // ---- scores = Q @ K^T ----
        float sc[8][4] = {};
        #pragma unroll
        for (int k8 = 0; k8 < HD; k8 += 8) {
            uint32_t af[4];
            af[0] = Qu[(r + g    ) * SQ + k8 + tg];
            af[1] = Qu[(r + g + 8) * SQ + k8 + tg];
            af[2] = Qu[(r + g    ) * SQ + k8 + tg + 4];
            af[3] = Qu[(r + g + 8) * SQ + k8 + tg + 4];
            #pragma unroll
            for (int f = 0; f < 8; f++) {
                uint32_t bf[2];
                bf[0] = Ku[(f * 8 + g) * SK + k8 + tg];
                bf[1] = Ku[(f * 8 + g) * SK + k8 + tg + 4];
                mma8(sc[f], af, bf);
            }
        }

        // ---- + mask (direct gmem fragment loads) ----
        #pragma unroll
        for (int f = 0; f < 8; f++) {
            float2 mv0 = *(const float2*)&mg[(size_t)(r + g    ) * S_KV + s0 + f * 8 + 2 * tg];
            float2 mv1 = *(const float2*)&mg[(size_t)(r + g + 8) * S_KV + s0 + f * 8 + 2 * tg];
            sc[f][0] += mv0.x; sc[f][1] += mv0.y;
            sc[f][2] += mv1.x; sc[f][3] += mv1.y;
        }

        // ---- online softmax (rows g and g+8; quad-replicated state) ----
        float mx0 = -1e30f, mx1 = -1e30f;
        #pragma unroll
        for (int f = 0; f < 8; f++) {
            mx0 = fmaxf(mx0, fmaxf(sc[f][0], sc[f][1]));
            mx1 = fmaxf(mx1, fmaxf(sc[f][2], sc[f][3]));
        }
        mx0 = fmaxf(mx0, __shfl_xor_sync(0xffffffffu, mx0, 1));
        mx0 = fmaxf(mx0, __shfl_xor_sync(0xffffffffu, mx0, 2));
        mx1 = fmaxf(mx1, __shfl_xor_sync(0xffffffffu, mx1, 1));
        mx1 = fmaxf(mx1, __shfl_xor_sync(0xffffffffu, mx1, 2));

        float mn0 = fmaxf(mr0, mx0), mn1 = fmaxf(mr1, mx1);
        float sc0 = __expf(mr0 - mn0), sc1 = __expf(mr1 - mn1);
        float sum0 = 0.f, sum1 = 0.f;
        #pragma unroll
        for (int f = 0; f < 8; f++) {
            sc[f][0] = __expf(sc[f][0] - mn0);
            sc[f][1] = __expf(sc[f][1] - mn0);
            sc[f][2] = __expf(sc[f][2] - mn1);
            sc[f][3] = __expf(sc[f][3] - mn1);
            sum0 += sc[f][0] + sc[f][1];
            sum1 += sc[f][2] + sc[f][3];
        }
        sum0 += __shfl_xor_sync(0xffffffffu, sum0, 1);
        sum0 += __shfl_xor_sync(0xffffffffu, sum0, 2);
        sum1 += __shfl_xor_sync(0xffffffffu, sum1, 1);
        sum1 += __shfl_xor_sync(0xffffffffu, sum1, 2);
        lr0 = lr0 * sc0 + sum0;  mr0 = mn0;
        lr1 = lr1 * sc1 + sum1;  mr1 = mn1;
        #pragma unroll
        for (int f = 0; f < 8; f++) {
            acc[f][0] *= sc0; acc[f][1] *= sc0;
            acc[f][2] *= sc1; acc[f][3] *= sc1;
        }

        // ---- store P (tf32) to this warp's private smem strip ----
        #pragma unroll
        for (int f = 0; f < 8; f++) {
            *(uint2*)&Pu[(r + g    ) * SP + f * 8 + 2 * tg] =
                make_uint2(f2t(sc[f][0]), f2t(sc[f][1]));
            *(uint2*)&Pu[(r + g + 8) * SP + f * 8 + 2 * tg] =
                make_uint2(f2t(sc[f][2]), f2t(sc[f][3]));
        }
        __syncwarp();

        // ---- acc += P @ V ----
        #pragma unroll
        for (int k8 = 0; k8 < BS; k8 += 8) {
            uint32_t af[4];
            af[0] = Pu[(r + g    ) * SP + k8 + tg];
            af[1] = Pu[(r + g + 8) * SP + k8 + tg];
            af[2] = Pu[(r + g    ) * SP + k8 + tg + 4];
            af[3] = Pu[(r + g + 8) * SP + k8 + tg + 4];
            #pragma unroll
            for (int f = 0; f < 8; f++) {
                uint32_t bf[2];
                bf[0] = Vu[(k8 + tg    ) * SV + f * 8 + g];
                bf[1] = Vu[(k8 + tg + 4) * SV + f * 8 + g];
                mma8(acc[f], af, bf);
            }
        }
    }

    // ---- normalize + write ctx [B,T,D] ----
    float inv0 = 1.f / lr0, inv1 = 1.f / lr1;
    int b = bh >> 4, h = bh & 15;
    float* cg = g_ctx + ((size_t)b * T_Q + t0 + r) * D_D + h * HD;
    #pragma unroll
    for (int f = 0; f < 8; f++) {
        *(float2*)&cg[(size_t)(g    ) * D_D + f * 8 + 2 * tg] =
            make_float2(acc[f][0] * inv0, acc[f][1] * inv0);
        *(float2*)&cg[(size_t)(g + 8) * D_D + f * 8 + 2 * tg] =
            make_float2(acc[f][2] * inv1, acc[f][3] * inv1);
    }
}

// ---------------------------------------------------------------------------
extern "C" void kernel_launch(void* const* d_in, const int* in_sizes, int n_in,
                              void* d_out, int out_size)
{
    const float* hs    = (const float*)d_in[0];
    const float* mask  = (const float*)d_in[1];
    const float* pos   = (const float*)d_in[2];
    const float* kv    = (const float*)d_in[3];
    const float* kvpos = (const float*)d_in[4];
    const float* Wq = (const float*)d_in[5];  const float* bq = (const float*)d_in[6];
    const float* Wk = (const float*)d_in[7];  const float* bk = (const float*)d_in[8];
    const float* Wv = (const float*)d_in[9];  const float* bv = (const float*)d_in[10];
    const float* Wo = (const float*)d_in[11]; const float* bo = (const float*)d_in[12];
    float* out = (float*)d_out;

    const int attn_smem = (128 * 68 + 64 * 68 + 64 * 72 + 128 * 68) * (int)sizeof(uint32_t);
    static int configured = 0;
    if (!configured) {
        cudaFuncSetAttribute(attn_mma, cudaFuncAttributeMaxDynamicSharedMemorySize,
                             attn_smem);
        configured = 1;
    }

    // Q projection: M = B*T = 2048
    proj_mma<0><<<dim3(D_D / 64, (B_B * T_Q) / 128), 256>>>(hs, pos, Wq, bq, nullptr, T_Q);
    // K projection: M = B*S = 8192
    proj_mma<1><<<dim3(D_D / 64, (B_B * S_KV) / 128), 256>>>(kv, kvpos, Wk, bk, nullptr, S_KV);
    // V projection
    proj_mma<2><<<dim3(D_D / 64, (B_B * S_KV) / 128), 256>>>(kv, nullptr, Wv, bv, nullptr, S_KV);
    // Attention
    attn_mma<<<dim3(T_Q / 128, B_B * H_H), 256, attn_smem>>>(mask);
    // Output projection
    proj_mma<3><<<dim3(D_D / 64, (B_B * T_Q) / 128), 256>>>(nullptr, nullptr, Wo, bo, out, T_Q);
}

// round 3
// speedup vs baseline: 3.5914x; 1.1733x over previous
#include <cuda_runtime.h>
#include <cuda_bf16.h>
#include <cstddef>
#include <cstdint>

#define T_Q  1024
#define B_B  2
#define S_KV 4096
#define D_D  1024
#define H_H  16
#define HD   64

// Scratch (device globals; allocations are forbidden). g_q/g_k/g_v hold
// tf32-rounded bit patterns so hot loops need no converts.
__device__ __align__(256) float g_q[(size_t)B_B * H_H * T_Q * HD];    //  8 MB
__device__ __align__(256) float g_k[(size_t)B_B * H_H * S_KV * HD];   // 32 MB
__device__ __align__(256) float g_v[(size_t)B_B * H_H * S_KV * HD];   // 32 MB
__device__ __align__(256) float g_ctx[(size_t)B_B * T_Q * D_D];       //  8 MB

// ---------------------------------------------------------------------------
__device__ __forceinline__ uint32_t f2t(float f) {
    uint32_t u; asm("cvt.rna.tf32.f32 %0, %1;" : "=r"(u) : "f"(f)); return u;
}

__device__ __forceinline__ void mma8(float* d, const uint32_t* a, const uint32_t* b) {
    asm volatile(
        "mma.sync.aligned.m16n8k8.row.col.f32.tf32.tf32.f32 "
        "{%0,%1,%2,%3},{%4,%5,%6,%7},{%8,%9},{%0,%1,%2,%3};"
        : "+f"(d[0]), "+f"(d[1]), "+f"(d[2]), "+f"(d[3])
        : "r"(a[0]), "r"(a[1]), "r"(a[2]), "r"(a[3]), "r"(b[0]), "r"(b[1]));
}

__device__ __forceinline__ void cp_async16(uint32_t saddr, const void* gaddr) {
    asm volatile("cp.async.cg.shared.global [%0], [%1], 16;"
                 :: "r"(saddr), "l"(gaddr) : "memory");
}
__device__ __forceinline__ void cp_commit() {
    asm volatile("cp.async.commit_group;" ::: "memory");
}
__device__ __forceinline__ void cp_wait0() {
    asm volatile("cp.async.wait_group 0;" ::: "memory");
}

// ---------------------------------------------------------------------------
// Fused projection GEMM via tf32 MMA, 128x128x16 tiles, reg->smem double
// buffered pipeline. C = (A [+A2]) @ W^T + bias.
// MODE 0: Q proj (hs+pos  -> g_q tf32, *0.125, head-split)
// MODE 1: K proj (kv+kvpos-> g_k tf32, head-split)
// MODE 2: V proj (kv      -> g_v tf32, head-split)
// MODE 3: O proj (g_ctx   -> d_out [T,B,D], fp32)
// ---------------------------------------------------------------------------
template <int MODE>
__global__ __launch_bounds__(256)
void proj_mma(const float* __restrict__ A, const float* __restrict__ A2,
              const float* __restrict__ W, const float* __restrict__ bias,
              float* __restrict__ out, int seqlen)
{
    constexpr int BM = 128, BN = 128, BK = 16, SA = 20;
    __shared__ __align__(16) uint32_t As[2][BM * SA];
    __shared__ __align__(16) uint32_t Ws[2][BN * SA];

    const int tid  = threadIdx.x;
    const int wid  = tid >> 5, lane = tid & 31;
    const int g    = lane >> 2, tg = lane & 3;
    const int wm   = wid >> 2, wn = wid & 3;     // 2 x 4 warp grid, warp = 64x32
    const int m0   = blockIdx.y * BM;
    const int n0   = blockIdx.x * BN;

    const int arow = tid >> 1;
    const int acol = (tid & 1) * 8;

    // Per-thread fixed source pointers (k advances along the row).
    const float* aptr;
    const float* a2ptr = nullptr;
    if (MODE == 3) {
        aptr = &g_ctx[(size_t)(m0 + arow) * D_D + acol];
    } else {
        const int bI  = m0 / seqlen;
        const int si0 = m0 - bI * seqlen;
        size_t base = (size_t)(si0 + arow) * (B_B * D_D) + (size_t)bI * D_D + acol;
        aptr = A + base;
        if (MODE == 0 || MODE == 1) a2ptr = A2 + base;
    }
    const float* wptr = &W[(size_t)(n0 + arow) * D_D + acol];

    float4 ra0, ra1, rw0, rw1;

    auto LD = [&](int k0) {
        ra0 = *(const float4*)(aptr + k0);
        ra1 = *(const float4*)(aptr + k0 + 4);
        if (MODE == 0 || MODE == 1) {
            float4 b0 = *(const float4*)(a2ptr + k0);
            float4 b1 = *(const float4*)(a2ptr + k0 + 4);
            ra0.x += b0.x; ra0.y += b0.y; ra0.z += b0.z; ra0.w += b0.w;
            ra1.x += b1.x; ra1.y += b1.y; ra1.z += b1.z; ra1.w += b1.w;
        }
        rw0 = *(const float4*)(wptr + k0);
        rw1 = *(const float4*)(wptr + k0 + 4);
    };
    auto ST = [&](int s) {
        uint32_t* pa = &As[s][arow * SA + acol];
        pa[0] = f2t(ra0.x); pa[1] = f2t(ra0.y); pa[2] = f2t(ra0.z); pa[3] = f2t(ra0.w);
        pa[4] = f2t(ra1.x); pa[5] = f2t(ra1.y); pa[6] = f2t(ra1.z); pa[7] = f2t(ra1.w);
        uint32_t* pw = &Ws[s][arow * SA + acol];
        pw[0] = f2t(rw0.x); pw[1] = f2t(rw0.y); pw[2] = f2t(rw0.z); pw[3] = f2t(rw0.w);
        pw[4] = f2t(rw1.x); pw[5] = f2t(rw1.y); pw[6] = f2t(rw1.z); pw[7] = f2t(rw1.w);
    };

    float acc[4][4][4] = {};

    constexpr int NST = D_D / BK;   // 64 stages
    LD(0);
    ST(0);
    LD(BK);

    for (int j = 0; j < NST; j++) {
        __syncthreads();
        if (j + 1 < NST) ST((j + 1) & 1);
        if (j + 2 < NST) LD((j + 2) * BK);

        const uint32_t* Ab = &As[j & 1][0];
        const uint32_t* Wb = &Ws[j & 1][0];
        #pragma unroll
        for (int k8 = 0; k8 < BK; k8 += 8) {
            uint32_t af[4][4], bf[4][2];
            #pragma unroll
            for (int im = 0; im < 4; im++) {
                int rm = wm * 64 + im * 16;
                af[im][0] = Ab[(rm + g    ) * SA + k8 + tg];
                af[im][1] = Ab[(rm + g + 8) * SA + k8 + tg];
                af[im][2] = Ab[(rm + g    ) * SA + k8 + tg + 4];
                af[im][3] = Ab[(rm + g + 8) * SA + k8 + tg + 4];
            }
            #pragma unroll
            for (int jn = 0; jn < 4; jn++) {
                int c = wn * 32 + jn * 8;
                bf[jn][0] = Wb[(c + g) * SA + k8 + tg];
                bf[jn][1] = Wb[(c + g) * SA + k8 + tg + 4];
            }
            #pragma unroll
            for (int im = 0; im < 4; im++)
                #pragma unroll
                for (int jn = 0; jn < 4; jn++)
                    mma8(acc[im][jn], af[im], bf[jn]);
        }
    }

    // Epilogue
    const int sl = (MODE == 3) ? T_Q : seqlen;
    #pragma unroll
    for (int im = 0; im < 4; im++) {
        #pragma unroll
        for (int rr = 0; rr < 2; rr++) {
            int m  = m0 + wm * 64 + im * 16 + g + rr * 8;
            int b  = m / sl;
            int si = m - b * sl;
            #pragma unroll
            for (int jn = 0; jn < 4; jn++) {
                int n = n0 + wn * 32 + jn * 8 + 2 * tg;
                float v0 = acc[im][jn][rr * 2 + 0] + bias[n];
                float v1 = acc[im][jn][rr * 2 + 1] + bias[n + 1];
                if (MODE == 0) {
                    v0 *= 0.125f; v1 *= 0.125f;
                    size_t o = (((size_t)b * H_H + (n >> 6)) * T_Q + si) * HD + (n & 63);
                    *(float2*)&g_q[o] = make_float2(__uint_as_float(f2t(v0)),
                                                    __uint_as_float(f2t(v1)));
                } else if (MODE == 1) {
                    size_t o = (((size_t)b * H_H + (n >> 6)) * S_KV + si) * HD + (n & 63);
                    *(float2*)&g_k[o] = make_float2(__uint_as_float(f2t(v0)),
                                                    __uint_as_float(f2t(v1)));
                } else if (MODE == 2) {
                    size_t o = (((size_t)b * H_H + (n >> 6)) * S_KV + si) * HD + (n & 63);
                    *(float2*)&g_v[o] = make_float2(__uint_as_float(f2t(v0)),
                                                    __uint_as_float(f2t(v1)));
                } else {
                    *(float2*)&out[(size_t)si * (B_B * D_D) + (size_t)b * D_D + n] =
                        make_float2(v0, v1);
                }
            }
        }
    }
}

// ---------------------------------------------------------------------------
// Flash attention, tf32 MMA, fully cp.async-pipelined:
//  - Q fragments live in registers (loaded once from gmem).
//  - K double-buffered: K(i+1) prefetched during softmax+PV(i).
//  - V prefetched during QK(i).
//  - mask(i) prefetched during QK(i) into the P buffer (dead at that point);
//    each lane reads exactly the mask elements it later overwrites with P,
//    so no extra synchronization is required for the aliasing.
// ---------------------------------------------------------------------------
__global__ __launch_bounds__(256, 2)
void attn_mma(const float* __restrict__ mask)
{
    constexpr int BQ = 128, BS = 64, SK = 68, SV = 72, SP = 72;
    extern __shared__ __align__(16) uint32_t smem[];
    uint32_t* Ku = smem;                 // [2][64*SK]
    uint32_t* Vu = Ku + 2 * 64 * SK;     // [64*SV]
    uint32_t* Pu = Vu + 64 * SV;         // [128*SP]  (mask in, P out)
    float*    Pf = (float*)Pu;

    const int tid  = threadIdx.x;
    const int wid  = tid >> 5, lane = tid & 31;
    const int g    = lane >> 2, tg = lane & 3;
    const int t0   = blockIdx.x * BQ;
    const int bh   = blockIdx.y;
    const int r    = wid * 16;

    const uint32_t* qg = (const uint32_t*)g_q + ((size_t)bh * T_Q + t0) * HD;
    const float*    kg = g_k + (size_t)bh * S_KV * HD;
    const float*    vg = g_v + (size_t)bh * S_KV * HD;
    const float*    mg = mask + (size_t)bh * T_Q * S_KV + (size_t)t0 * S_KV;

    // Q fragments in registers (already tf32 bits)
    uint32_t qf[8][4];
    #pragma unroll
    for (int kb = 0; kb < 8; kb++) {
        qf[kb][0] = qg[(size_t)(r + g    ) * HD + kb * 8 + tg];
        qf[kb][1] = qg[(size_t)(r + g + 8) * HD + kb * 8 + tg];
        qf[kb][2] = qg[(size_t)(r + g    ) * HD + kb * 8 + tg + 4];
        qf[kb][3] = qg[(size_t)(r + g + 8) * HD + kb * 8 + tg + 4];
    }

    const uint32_t ku_s = (uint32_t)__cvta_generic_to_shared(Ku);
    const uint32_t vu_s = (uint32_t)__cvta_generic_to_shared(Vu);
    const uint32_t pu_s = (uint32_t)__cvta_generic_to_shared(Pu);

    auto loadK = [&](int s0, int buf) {
        #pragma unroll
        for (int i = 0; i < 4; i++) {
            int idx = tid + i * 256;
            int row = idx >> 4, c4 = (idx & 15) * 4;
            cp_async16(ku_s + (uint32_t)(buf * 64 * SK + row * SK + c4) * 4,
                       kg + (size_t)(s0 + row) * HD + c4);
        }
    };
    auto loadV = [&](int s0) {
        #pragma unroll
        for (int i = 0; i < 4; i++) {
            int idx = tid + i * 256;
            int row = idx >> 4, c4 = (idx & 15) * 4;
            cp_async16(vu_s + (uint32_t)(row * SV + c4) * 4,
                       vg + (size_t)(s0 + row) * HD + c4);
        }
    };
    auto loadM = [&](int s0) {   // warp loads its own 16 mask rows
        #pragma unroll
        for (int i = 0; i < 8; i++) {
            int idx = lane + i * 32;
            int row = idx >> 4, c4 = (idx & 15) * 4;
            cp_async16(pu_s + (uint32_t)((r + row) * SP + c4) * 4,
                       mg + (size_t)(r + row) * S_KV + s0 + c4);
        }
    };

    loadK(0, 0);
    cp_commit();

    float acc[8][4] = {};
    float mr0 = -1e30f, mr1 = -1e30f, lr0 = 0.f, lr1 = 0.f;

    constexpr int NT = S_KV / BS;   // 64 tiles
    for (int it = 0; it < NT; it++) {
        const int s0 = it * BS;
        cp_wait0();                 // K(it) arrived
        __syncthreads();            // K visible; V/P buffers free
        loadV(s0);
        loadM(s0);
        cp_commit();

        // ---- scores = Q @ K^T (overlaps V+mask loads) ----
        const uint32_t* Kb = Ku + (it & 1) * 64 * SK;
        float sc[8][4] = {};
        #pragma unroll
        for (int k8 = 0; k8 < 8; k8++) {
            #pragma unroll
            for (int f = 0; f < 8; f++) {
                uint32_t bf[2];
                bf[0] = Kb[(f * 8 + g) * SK + k8 * 8 + tg];
                bf[1] = Kb[(f * 8 + g) * SK + k8 * 8 + tg + 4];
                mma8(sc[f], qf[k8], bf);
            }
        }

        cp_wait0();                 // V + mask arrived
        __syncthreads();            // V visible block-wide; K(it) fully consumed
        if (it + 1 < NT) {          // prefetch K(it+1) (overlaps softmax + PV)
            loadK(s0 + BS, (it + 1) & 1);
            cp_commit();
        }

        // ---- + mask (from smem) ----
        #pragma unroll
        for (int f = 0; f < 8; f++) {
            float2 m0v = *(const float2*)&Pf[(r + g    ) * SP + f * 8 + 2 * tg];
            float2 m1v = *(const float2*)&Pf[(r + g + 8) * SP + f * 8 + 2 * tg];
            sc[f][0] += m0v.x; sc[f][1] += m0v.y;
            sc[f][2] += m1v.x; sc[f][3] += m1v.y;
        }

        // ---- online softmax (rows g and g+8; quad-replicated state) ----
        float mx0 = -1e30f, mx1 = -1e30f;
        #pragma unroll
        for (int f = 0; f < 8; f++) {
            mx0 = fmaxf(mx0, fmaxf(sc[f][0], sc[f][1]));
            mx1 = fmaxf(mx1, fmaxf(sc[f][2], sc[f][3]));
        }
        mx0 = fmaxf(mx0, __shfl_xor_sync(0xffffffffu, mx0, 1));
        mx0 = fmaxf(mx0, __shfl_xor_sync(0xffffffffu, mx0, 2));
        mx1 = fmaxf(mx1, __shfl_xor_sync(0xffffffffu, mx1, 1));
        mx1 = fmaxf(mx1, __shfl_xor_sync(0xffffffffu, mx1, 2));

        float mn0 = fmaxf(mr0, mx0), mn1 = fmaxf(mr1, mx1);
        float e0 = __expf(mr0 - mn0), e1 = __expf(mr1 - mn1);
        float sum0 = 0.f, sum1 = 0.f;
        #pragma unroll
        for (int f = 0; f < 8; f++) {
            sc[f][0] = __expf(sc[f][0] - mn0);
            sc[f][1] = __expf(sc[f][1] - mn0);
            sc[f][2] = __expf(sc[f][2] - mn1);
            sc[f][3] = __expf(sc[f][3] - mn1);
            sum0 += sc[f][0] + sc[f][1];
            sum1 += sc[f][2] + sc[f][3];
        }
        sum0 += __shfl_xor_sync(0xffffffffu, sum0, 1);
        sum0 += __shfl_xor_sync(0xffffffffu, sum0, 2);
        sum1 += __shfl_xor_sync(0xffffffffu, sum1, 1);
        sum1 += __shfl_xor_sync(0xffffffffu, sum1, 2);
        lr0 = lr0 * e0 + sum0;  mr0 = mn0;
        lr1 = lr1 * e1 + sum1;  mr1 = mn1;
        #pragma unroll
        for (int f = 0; f < 8; f++) {
            acc[f][0] *= e0; acc[f][1] *= e0;
            acc[f][2] *= e1; acc[f][3] *= e1;
        }

        // ---- store P (tf32) over the mask strip (per-lane identical addrs) ----
        #pragma unroll
        for (int f = 0; f < 8; f++) {
            *(uint2*)&Pu[(r + g    ) * SP + f * 8 + 2 * tg] =
                make_uint2(f2t(sc[f][0]), f2t(sc[f][1]));
            *(uint2*)&Pu[(r + g + 8) * SP + f * 8 + 2 * tg] =
                make_uint2(f2t(sc[f][2]), f2t(sc[f][3]));
        }
        __syncwarp();

        // ---- acc += P @ V ----
        #pragma unroll
        for (int k8 = 0; k8 < 8; k8++) {
            uint32_t af[4];
            af[0] = Pu[(r + g    ) * SP + k8 * 8 + tg];
            af[1] = Pu[(r + g + 8) * SP + k8 * 8 + tg];
            af[2] = Pu[(r + g    ) * SP + k8 * 8 + tg + 4];
            af[3] = Pu[(r + g + 8) * SP + k8 * 8 + tg + 4];
            #pragma unroll
            for (int f = 0; f < 8; f++) {
                uint32_t bf[2];
                bf[0] = Vu[(k8 * 8 + tg    ) * SV + f * 8 + g];
                bf[1] = Vu[(k8 * 8 + tg + 4) * SV + f * 8 + g];
                mma8(acc[f], af, bf);
            }
        }
    }

    // ---- normalize + write ctx [B,T,D] ----
    float inv0 = 1.f / lr0, inv1 = 1.f / lr1;
    int b = bh >> 4, h = bh & 15;
    float* cg = g_ctx + ((size_t)b * T_Q + t0 + r) * D_D + h * HD;
    #pragma unroll
    for (int f = 0; f < 8; f++) {
        *(float2*)&cg[(size_t)(g    ) * D_D + f * 8 + 2 * tg] =
            make_float2(acc[f][0] * inv0, acc[f][1] * inv0);
        *(float2*)&cg[(size_t)(g + 8) * D_D + f * 8 + 2 * tg] =
            make_float2(acc[f][2] * inv1, acc[f][3] * inv1);
    }
}

// ---------------------------------------------------------------------------
extern "C" void kernel_launch(void* const* d_in, const int* in_sizes, int n_in,
                              void* d_out, int out_size)
{
    const float* hs    = (const float*)d_in[0];
    const float* mask  = (const float*)d_in[1];
    const float* pos   = (const float*)d_in[2];
    const float* kv    = (const float*)d_in[3];
    const float* kvpos = (const float*)d_in[4];
    const float* Wq = (const float*)d_in[5];  const float* bq = (const float*)d_in[6];
    const float* Wk = (const float*)d_in[7];  const float* bk = (const float*)d_in[8];
    const float* Wv = (const float*)d_in[9];  const float* bv = (const float*)d_in[10];
    const float* Wo = (const float*)d_in[11]; const float* bo = (const float*)d_in[12];
    float* out = (float*)d_out;

    const int attn_smem = (2 * 64 * 68 + 64 * 72 + 128 * 72) * (int)sizeof(uint32_t);
    cudaFuncSetAttribute(attn_mma, cudaFuncAttributeMaxDynamicSharedMemorySize,
                         attn_smem);

    // Q projection: M = B*T = 2048
    proj_mma<0><<<dim3(D_D / 128, (B_B * T_Q) / 128), 256>>>(hs, pos, Wq, bq, nullptr, T_Q);
    // K projection: M = B*S = 8192
    proj_mma<1><<<dim3(D_D / 128, (B_B * S_KV) / 128), 256>>>(kv, kvpos, Wk, bk, nullptr, S_KV);
    // V projection
    proj_mma<2><<<dim3(D_D / 128, (B_B * S_KV) / 128), 256>>>(kv, nullptr, Wv, bv, nullptr, S_KV);
    // Attention
    attn_mma<<<dim3(T_Q / 128, B_B * H_H), 256, attn_smem>>>(mask);
    // Output projection
    proj_mma<3><<<dim3(D_D / 128, (B_B * T_Q) / 128), 256>>>(nullptr, nullptr, Wo, bo, out, T_Q);
}

// round 4
// speedup vs baseline: 4.6622x; 1.2982x over previous
#include <cuda_runtime.h>
#include <cuda_bf16.h>
#include <cstddef>
#include <cstdint>

#define T_Q  1024
#define B_B  2
#define S_KV 4096
#define D_D  1024
#define H_H  16
#define HD   64

// Scratch (device globals; allocations are forbidden). g_q/g_k/g_v hold
// tf32-rounded bit patterns so hot loops need no converts.
__device__ __align__(256) float g_q[(size_t)B_B * H_H * T_Q * HD];    //  8 MB
__device__ __align__(256) float g_k[(size_t)B_B * H_H * S_KV * HD];   // 32 MB
__device__ __align__(256) float g_v[(size_t)B_B * H_H * S_KV * HD];   // 32 MB
__device__ __align__(256) float g_ctx[(size_t)B_B * T_Q * D_D];       //  8 MB
__device__ __align__(256) float g_shs[(size_t)T_Q * B_B * D_D];       //  8 MB (hs+pos)
__device__ __align__(256) float g_skv[(size_t)S_KV * B_B * D_D];      // 32 MB (kv+kvpos)

// ---------------------------------------------------------------------------
__device__ __forceinline__ uint32_t f2t(float f) {
    uint32_t u; asm("cvt.rna.tf32.f32 %0, %1;" : "=r"(u) : "f"(f)); return u;
}

__device__ __forceinline__ void mma8(float* d, const uint32_t* a, const uint32_t* b) {
    asm volatile(
        "mma.sync.aligned.m16n8k8.row.col.f32.tf32.tf32.f32 "
        "{%0,%1,%2,%3},{%4,%5,%6,%7},{%8,%9},{%0,%1,%2,%3};"
        : "+f"(d[0]), "+f"(d[1]), "+f"(d[2]), "+f"(d[3])
        : "r"(a[0]), "r"(a[1]), "r"(a[2]), "r"(a[3]), "r"(b[0]), "r"(b[1]));
}

__device__ __forceinline__ void cp_async16(uint32_t saddr, const void* gaddr) {
    asm volatile("cp.async.cg.shared.global [%0], [%1], 16;"
                 :: "r"(saddr), "l"(gaddr) : "memory");
}
__device__ __forceinline__ void cp_commit() {
    asm volatile("cp.async.commit_group;" ::: "memory");
}
__device__ __forceinline__ void cp_wait0() {
    asm volatile("cp.async.wait_group 0;" ::: "memory");
}
__device__ __forceinline__ void cp_wait1() {
    asm volatile("cp.async.wait_group 1;" ::: "memory");
}

// ---------------------------------------------------------------------------
// Elementwise pre-sum: o = a + b (float4 granularity).
// ---------------------------------------------------------------------------
__global__ void add_vec(const float4* __restrict__ a, const float4* __restrict__ b,
                        float4* __restrict__ o, int n)
{
    int i = blockIdx.x * blockDim.x + threadIdx.x;
    if (i < n) {
        float4 x = a[i], y = b[i];
        o[i] = make_float4(x.x + y.x, x.y + y.y, x.z + y.z, x.w + y.w);
    }
}

// ---------------------------------------------------------------------------
// Unified projection GEMM, tf32 MMA, 128x128x16 tiles, 3-stage cp.async
// pipeline, tf32 convert at fragment-load time.
// mode 0: Q (g_shs -> g_q tf32, *0.125, head-split)
// mode 1: K (g_skv -> g_k tf32, head-split)
// mode 2: V (kv    -> g_v tf32, head-split)
// mode 3: O (g_ctx -> out [T,B,D] fp32)
// force_mode < 0: merged QKV grid (K:0..511, V:512..1023, Q:1024..1151).
// ---------------------------------------------------------------------------
__global__ __launch_bounds__(256, 2)
void proj_all(const float* __restrict__ kv,
              const float* __restrict__ Wq, const float* __restrict__ bq,
              const float* __restrict__ Wk, const float* __restrict__ bk,
              const float* __restrict__ Wv, const float* __restrict__ bv,
              const float* __restrict__ Wo, const float* __restrict__ bo,
              float* __restrict__ out, int force_mode)
{
    constexpr int SA = 20, STG = 5120;           // floats per stage (A 2560 + W 2560)
    extern __shared__ __align__(16) float sh[];  // [3][STG]

    const int tid  = threadIdx.x;
    const int wid  = tid >> 5, lane = tid & 31;
    const int g    = lane >> 2, tg = lane & 3;
    const int wm   = wid >> 2, wn = wid & 3;     // 2 x 4 warps, warp = 64x32

    int mode, local;
    if (force_mode >= 0) { mode = force_mode; local = blockIdx.x; }
    else {
        int c = blockIdx.x;
        if (c < 512)       { mode = 1; local = c; }
        else if (c < 1024) { mode = 2; local = c - 512; }
        else               { mode = 0; local = c - 1024; }
    }
    const int m0 = (local >> 3) * 128;
    const int n0 = (local & 7) * 128;

    const float* Ap; const float* Wp; const float* bp; int sl;
    if (mode == 0)      { Ap = g_shs;  Wp = Wq; bp = bq; sl = T_Q;  }
    else if (mode == 1) { Ap = g_skv;  Wp = Wk; bp = bk; sl = S_KV; }
    else if (mode == 2) { Ap = kv;     Wp = Wv; bp = bv; sl = S_KV; }
    else                { Ap = g_ctx;  Wp = Wo; bp = bo; sl = T_Q;  }

    const int bI  = m0 / sl;
    const int si0 = m0 - bI * sl;

    // Per-thread cp.async source pointers (2 x 16B chunks each for A and W)
    const int r0 = tid >> 2,            c0 = (tid & 3) * 4;
    const int r1 = (tid + 256) >> 2,    c1 = (tid & 3) * 4;
    const float* ap0;
    const float* ap1;
    if (mode == 3) {
        ap0 = Ap + (size_t)(m0 + r0) * D_D + c0;
        ap1 = Ap + (size_t)(m0 + r1) * D_D + c1;
    } else {
        ap0 = Ap + (size_t)(si0 + r0) * (B_B * D_D) + (size_t)bI * D_D + c0;
        ap1 = Ap + (size_t)(si0 + r1) * (B_B * D_D) + (size_t)bI * D_D + c1;
    }
    const float* wp0 = Wp + (size_t)(n0 + r0) * D_D + c0;
    const float* wp1 = Wp + (size_t)(n0 + r1) * D_D + c1;

    const uint32_t sb = (uint32_t)__cvta_generic_to_shared(sh);
    const uint32_t sa0 = sb + (uint32_t)(r0 * SA + c0) * 4;
    const uint32_t sa1 = sb + (uint32_t)(r1 * SA + c1) * 4;
    const uint32_t sw0 = sa0 + 2560 * 4;
    const uint32_t sw1 = sa1 + 2560 * 4;

    auto issue = [&](int j) {
        const uint32_t so = (uint32_t)((j % 3) * STG) * 4;
        const int k0 = j * 16;
        cp_async16(sa0 + so, ap0 + k0);
        cp_async16(sa1 + so, ap1 + k0);
        cp_async16(sw0 + so, wp0 + k0);
        cp_async16(sw1 + so, wp1 + k0);
        cp_commit();
    };

    float acc[4][4][4] = {};
    constexpr int NST = D_D / 16;   // 64 stages
    issue(0);
    issue(1);

    for (int j = 0; j < NST; j++) {
        cp_wait1();                 // stage j landed (<=1 group pending)
        __syncthreads();            // stage j visible; stage j-1 buffer free
        if (j + 2 < NST) issue(j + 2);

        const float* Ab = sh + (j % 3) * STG;
        const float* Wb = Ab + 2560;
        #pragma unroll
        for (int k8 = 0; k8 < 16; k8 += 8) {
            uint32_t af[4][4], bf[4][2];
            #pragma unroll
            for (int im = 0; im < 4; im++) {
                int rm = wm * 64 + im * 16;
                af[im][0] = f2t(Ab[(rm + g    ) * SA + k8 + tg]);
                af[im][1] = f2t(Ab[(rm + g + 8) * SA + k8 + tg]);
                af[im][2] = f2t(Ab[(rm + g    ) * SA + k8 + tg + 4]);
                af[im][3] = f2t(Ab[(rm + g + 8) * SA + k8 + tg + 4]);
            }
            #pragma unroll
            for (int jn = 0; jn < 4; jn++) {
                int c = wn * 32 + jn * 8;
                bf[jn][0] = f2t(Wb[(c + g) * SA + k8 + tg]);
                bf[jn][1] = f2t(Wb[(c + g) * SA + k8 + tg + 4]);
            }
            #pragma unroll
            for (int im = 0; im < 4; im++)
                #pragma unroll
                for (int jn = 0; jn < 4; jn++)
                    mma8(acc[im][jn], af[im], bf[jn]);
        }
    }

    // Epilogue
    #pragma unroll
    for (int im = 0; im < 4; im++) {
        #pragma unroll
        for (int rr = 0; rr < 2; rr++) {
            int m  = m0 + wm * 64 + im * 16 + g + rr * 8;
            int si = m - bI * sl;
            #pragma unroll
            for (int jn = 0; jn < 4; jn++) {
                int n = n0 + wn * 32 + jn * 8 + 2 * tg;
                float v0 = acc[im][jn][rr * 2 + 0] + bp[n];
                float v1 = acc[im][jn][rr * 2 + 1] + bp[n + 1];
                if (mode == 0) {
                    v0 *= 0.125f; v1 *= 0.125f;
                    size_t o = (((size_t)bI * H_H + (n >> 6)) * T_Q + si) * HD + (n & 63);
                    *(float2*)&g_q[o] = make_float2(__uint_as_float(f2t(v0)),
                                                    __uint_as_float(f2t(v1)));
                } else if (mode == 1) {
                    size_t o = (((size_t)bI * H_H + (n >> 6)) * S_KV + si) * HD + (n & 63);
                    *(float2*)&g_k[o] = make_float2(__uint_as_float(f2t(v0)),
                                                    __uint_as_float(f2t(v1)));
                } else if (mode == 2) {
                    size_t o = (((size_t)bI * H_H + (n >> 6)) * S_KV + si) * HD + (n & 63);
                    *(float2*)&g_v[o] = make_float2(__uint_as_float(f2t(v0)),
                                                    __uint_as_float(f2t(v1)));
                } else {
                    *(float2*)&out[(size_t)si * (B_B * D_D) + (size_t)bI * D_D + n] =
                        make_float2(v0, v1);
                }
            }
        }
    }
}

// ---------------------------------------------------------------------------
// Flash attention, tf32 MMA, cp.async pipelined (unchanged from R3).
// ---------------------------------------------------------------------------
__global__ __launch_bounds__(256, 2)
void attn_mma(const float* __restrict__ mask)
{
    constexpr int BQ = 128, BS = 64, SK = 68, SV = 72, SP = 72;
    extern __shared__ __align__(16) uint32_t smem[];
    uint32_t* Ku = smem;                 // [2][64*SK]
    uint32_t* Vu = Ku + 2 * 64 * SK;     // [64*SV]
    uint32_t* Pu = Vu + 64 * SV;         // [128*SP]  (mask in, P out)
    float*    Pf = (float*)Pu;

    const int tid  = threadIdx.x;
    const int wid  = tid >> 5, lane = tid & 31;
    const int g    = lane >> 2, tg = lane & 3;
    const int t0   = blockIdx.x * BQ;
    const int bh   = blockIdx.y;
    const int r    = wid * 16;

    const uint32_t* qg = (const uint32_t*)g_q + ((size_t)bh * T_Q + t0) * HD;
    const float*    kg = g_k + (size_t)bh * S_KV * HD;
    const float*    vg = g_v + (size_t)bh * S_KV * HD;
    const float*    mg = mask + (size_t)bh * T_Q * S_KV + (size_t)t0 * S_KV;

    uint32_t qf[8][4];
    #pragma unroll
    for (int kb = 0; kb < 8; kb++) {
        qf[kb][0] = qg[(size_t)(r + g    ) * HD + kb * 8 + tg];
        qf[kb][1] = qg[(size_t)(r + g + 8) * HD + kb * 8 + tg];
        qf[kb][2] = qg[(size_t)(r + g    ) * HD + kb * 8 + tg + 4];
        qf[kb][3] = qg[(size_t)(r + g + 8) * HD + kb * 8 + tg + 4];
    }

    const uint32_t ku_s = (uint32_t)__cvta_generic_to_shared(Ku);
    const uint32_t vu_s = (uint32_t)__cvta_generic_to_shared(Vu);
    const uint32_t pu_s = (uint32_t)__cvta_generic_to_shared(Pu);

    auto loadK = [&](int s0, int buf) {
        #pragma unroll
        for (int i = 0; i < 4; i++) {
            int idx = tid + i * 256;
            int row = idx >> 4, c4 = (idx & 15) * 4;
            cp_async16(ku_s + (uint32_t)(buf * 64 * SK + row * SK + c4) * 4,
                       kg + (size_t)(s0 + row) * HD + c4);
        }
    };
    auto loadV = [&](int s0) {
        #pragma unroll
        for (int i = 0; i < 4; i++) {
            int idx = tid + i * 256;
            int row = idx >> 4, c4 = (idx & 15) * 4;
            cp_async16(vu_s + (uint32_t)(row * SV + c4) * 4,
                       vg + (size_t)(s0 + row) * HD + c4);
        }
    };
    auto loadM = [&](int s0) {
        #pragma unroll
        for (int i = 0; i < 8; i++) {
            int idx = lane + i * 32;
            int row = idx >> 4, c4 = (idx & 15) * 4;
            cp_async16(pu_s + (uint32_t)((r + row) * SP + c4) * 4,
                       mg + (size_t)(r + row) * S_KV + s0 + c4);
        }
    };

    loadK(0, 0);
    cp_commit();

    float acc[8][4] = {};
    float mr0 = -1e30f, mr1 = -1e30f, lr0 = 0.f, lr1 = 0.f;

    constexpr int NT = S_KV / BS;
    for (int it = 0; it < NT; it++) {
        const int s0 = it * BS;
        cp_wait0();
        __syncthreads();
        loadV(s0);
        loadM(s0);
        cp_commit();

        const uint32_t* Kb = Ku + (it & 1) * 64 * SK;
        float sc[8][4] = {};
        #pragma unroll
        for (int k8 = 0; k8 < 8; k8++) {
            #pragma unroll
            for (int f = 0; f < 8; f++) {
                uint32_t bf[2];
                bf[0] = Kb[(f * 8 + g) * SK + k8 * 8 + tg];
                bf[1] = Kb[(f * 8 + g) * SK + k8 * 8 + tg + 4];
                mma8(sc[f], qf[k8], bf);
            }
        }

        cp_wait0();
        __syncthreads();
        if (it + 1 < NT) {
            loadK(s0 + BS, (it + 1) & 1);
            cp_commit();
        }

        #pragma unroll
        for (int f = 0; f < 8; f++) {
            float2 m0v = *(const float2*)&Pf[(r + g    ) * SP + f * 8 + 2 * tg];
            float2 m1v = *(const float2*)&Pf[(r + g + 8) * SP + f * 8 + 2 * tg];
            sc[f][0] += m0v.x; sc[f][1] += m0v.y;
            sc[f][2] += m1v.x; sc[f][3] += m1v.y;
        }

        float mx0 = -1e30f, mx1 = -1e30f;
        #pragma unroll
        for (int f = 0; f < 8; f++) {
            mx0 = fmaxf(mx0, fmaxf(sc[f][0], sc[f][1]));
            mx1 = fmaxf(mx1, fmaxf(sc[f][2], sc[f][3]));
        }
        mx0 = fmaxf(mx0, __shfl_xor_sync(0xffffffffu, mx0, 1));
        mx0 = fmaxf(mx0, __shfl_xor_sync(0xffffffffu, mx0, 2));
        mx1 = fmaxf(mx1, __shfl_xor_sync(0xffffffffu, mx1, 1));
        mx1 = fmaxf(mx1, __shfl_xor_sync(0xffffffffu, mx1, 2));

        float mn0 = fmaxf(mr0, mx0), mn1 = fmaxf(mr1, mx1);
        float e0 = __expf(mr0 - mn0), e1 = __expf(mr1 - mn1);
        float sum0 = 0.f, sum1 = 0.f;
        #pragma unroll
        for (int f = 0; f < 8; f++) {
            sc[f][0] = __expf(sc[f][0] - mn0);
            sc[f][1] = __expf(sc[f][1] - mn0);
            sc[f][2] = __expf(sc[f][2] - mn1);
            sc[f][3] = __expf(sc[f][3] - mn1);
            sum0 += sc[f][0] + sc[f][1];
            sum1 += sc[f][2] + sc[f][3];
        }
        sum0 += __shfl_xor_sync(0xffffffffu, sum0, 1);
        sum0 += __shfl_xor_sync(0xffffffffu, sum0, 2);
        sum1 += __shfl_xor_sync(0xffffffffu, sum1, 1);
        sum1 += __shfl_xor_sync(0xffffffffu, sum1, 2);
        lr0 = lr0 * e0 + sum0;  mr0 = mn0;
        lr1 = lr1 * e1 + sum1;  mr1 = mn1;
        #pragma unroll
        for (int f = 0; f < 8; f++) {
            acc[f][0] *= e0; acc[f][1] *= e0;
            acc[f][2] *= e1; acc[f][3] *= e1;
        }

        #pragma unroll
        for (int f = 0; f < 8; f++) {
            *(uint2*)&Pu[(r + g    ) * SP + f * 8 + 2 * tg] =
                make_uint2(f2t(sc[f][0]), f2t(sc[f][1]));
            *(uint2*)&Pu[(r + g + 8) * SP + f * 8 + 2 * tg] =
                make_uint2(f2t(sc[f][2]), f2t(sc[f][3]));
        }
        __syncwarp();

        #pragma unroll
        for (int k8 = 0; k8 < 8; k8++) {
            uint32_t af[4];
            af[0] = Pu[(r + g    ) * SP + k8 * 8 + tg];
            af[1] = Pu[(r + g + 8) * SP + k8 * 8 + tg];
            af[2] = Pu[(r + g    ) * SP + k8 * 8 + tg + 4];
            af[3] = Pu[(r + g + 8) * SP + k8 * 8 + tg + 4];
            #pragma unroll
            for (int f = 0; f < 8; f++) {
                uint32_t bf[2];
                bf[0] = Vu[(k8 * 8 + tg    ) * SV + f * 8 + g];
                bf[1] = Vu[(k8 * 8 + tg + 4) * SV + f * 8 + g];
                mma8(acc[f], af, bf);
            }
        }
    }

    float inv0 = 1.f / lr0, inv1 = 1.f / lr1;
    int b = bh >> 4, h = bh & 15;
    float* cg = g_ctx + ((size_t)b * T_Q + t0 + r) * D_D + h * HD;
    #pragma unroll
    for (int f = 0; f < 8; f++) {
        *(float2*)&cg[(size_t)(g    ) * D_D + f * 8 + 2 * tg] =
            make_float2(acc[f][0] * inv0, acc[f][1] * inv0);
        *(float2*)&cg[(size_t)(g + 8) * D_D + f * 8 + 2 * tg] =
            make_float2(acc[f][2] * inv1, acc[f][3] * inv1);
    }
}

// ---------------------------------------------------------------------------
extern "C" void kernel_launch(void* const* d_in, const int* in_sizes, int n_in,
                              void* d_out, int out_size)
{
    const float* hs    = (const float*)d_in[0];
    const float* mask  = (const float*)d_in[1];
    const float* pos   = (const float*)d_in[2];
    const float* kv    = (const float*)d_in[3];
    const float* kvpos = (const float*)d_in[4];
    const float* Wq = (const float*)d_in[5];  const float* bq = (const float*)d_in[6];
    const float* Wk = (const float*)d_in[7];  const float* bk = (const float*)d_in[8];
    const float* Wv = (const float*)d_in[9];  const float* bv = (const float*)d_in[10];
    const float* Wo = (const float*)d_in[11]; const float* bo = (const float*)d_in[12];
    float* out = (float*)d_out;

    const int attn_smem = (2 * 64 * 68 + 64 * 72 + 128 * 72) * (int)sizeof(uint32_t);
    const int proj_smem = 3 * 5120 * (int)sizeof(float);   // 61440
    cudaFuncSetAttribute(attn_mma, cudaFuncAttributeMaxDynamicSharedMemorySize,
                         attn_smem);
    cudaFuncSetAttribute(proj_all, cudaFuncAttributeMaxDynamicSharedMemorySize,
                         proj_smem);

    float* shs_d = nullptr;  cudaGetSymbolAddress((void**)&shs_d, g_shs);
    float* skv_d = nullptr;  cudaGetSymbolAddress((void**)&skv_d, g_skv);

    // Pre-sum inputs: hs+pos (2M float), kv+kvpos (8M float)
    {
        int n4 = (T_Q * B_B * D_D) / 4;
        add_vec<<<(n4 + 255) / 256, 256>>>((const float4*)hs, (const float4*)pos,
                                           (float4*)shs_d, n4);
        n4 = (S_KV * B_B * D_D) / 4;
        add_vec<<<(n4 + 255) / 256, 256>>>((const float4*)kv, (const float4*)kvpos,
                                           (float4*)skv_d, n4);
    }

    // Merged Q/K/V projections: 512 (K) + 512 (V) + 128 (Q) CTAs
    proj_all<<<1152, 256, proj_smem>>>(kv, Wq, bq, Wk, bk, Wv, bv, Wo, bo,
                                       nullptr, -1);
    // Attention
    attn_mma<<<dim3(T_Q / 128, B_B * H_H), 256, attn_smem>>>(mask);
    // Output projection
    proj_all<<<128, 256, proj_smem>>>(kv, Wq, bq, Wk, bk, Wv, bv, Wo, bo,
                                      out, 3);
}